// round 5
// baseline (speedup 1.0000x reference)
#include <cuda_runtime.h>
#include <math.h>

#define Bn 4
#define Cc 64
#define Oo 64
#define Hh 128
#define Ww 128
#define HW (Hh*Ww)

// ---------------- device scratch ----------------
__device__ float g_xt[Bn*HW*Cc];      // x as [b][h][w][c]
__device__ float g_wt[9*Cc*Oo];       // dcn_w as [tap][c][o]
__device__ float g_ow[9*Cc*32];       // offset_w as [tap][c][jq][8], j = jq*7+idx (idx<7, j<27)
__device__ float g_offx[Bn*9*HW];
__device__ float g_offy[Bn*9*HW];
__device__ float g_mask[Bn*9*HW];
__device__ float g_stats[2*Oo];

// ---------------- f32x2 helpers ----------------
__device__ __forceinline__ unsigned long long f2pack(float lo, float hi) {
    unsigned long long r;
    asm("mov.b64 %0, {%1, %2};" : "=l"(r)
        : "r"(__float_as_uint(lo)), "r"(__float_as_uint(hi)));
    return r;
}
__device__ __forceinline__ void f2unpack(unsigned long long v, float &lo, float &hi) {
    unsigned int a, b;
    asm("mov.b64 {%0, %1}, %2;" : "=r"(a), "=r"(b) : "l"(v));
    lo = __uint_as_float(a); hi = __uint_as_float(b);
}
__device__ __forceinline__ void ffma2(unsigned long long &d,
                                      unsigned long long a, unsigned long long b) {
    asm("fma.rn.f32x2 %0, %1, %2, %0;" : "+l"(d) : "l"(a), "l"(b));
}

// ---------------- K0: NCHW -> NHWC ----------------
__global__ void k_transpose(const float* __restrict__ x) {
    __shared__ float tile[32][65];
    int b = blockIdx.y, hw0 = blockIdx.x * 32;
    int tx = threadIdx.x, ty = threadIdx.y;
#pragma unroll
    for (int cc = 0; cc < 8; cc++) {
        int c = cc * 8 + ty;
        tile[tx][c] = x[(b*Cc + c)*HW + hw0 + tx];
    }
    __syncthreads();
#pragma unroll
    for (int rr = 0; rr < 4; rr++) {
        int hw = rr * 8 + ty;
        float* dst = g_xt + (size_t)(b*HW + hw0 + hw) * Cc;
        dst[tx]      = tile[hw][tx];
        dst[tx + 32] = tile[hw][tx + 32];
    }
}

// ---------------- K0b: weight re-layouts ----------------
__global__ void k_wt(const float* __restrict__ dcn_w) {
    int i = blockIdx.x * 256 + threadIdx.x;
    if (i < 9*Cc*Oo) {
        int o = i & 63, c = (i >> 6) & 63, k = i >> 12;
        g_wt[i] = dcn_w[(o*Cc + c)*9 + k];
    }
}
// offset_w -> [tap][c][jq][8]: slot idx of quarter jq maps to j = jq*7+idx (idx<7, j<27)
__global__ void k_owt(const float* __restrict__ ow) {
    int i = blockIdx.x * 256 + threadIdx.x;
    if (i < 9*Cc*32) {
        int slot = i & 31, c = (i >> 5) & 63, tap = i >> 11;
        int ky = tap / 3, kx = tap % 3;
        int jq = slot >> 3, idx = slot & 7;
        int j = jq*7 + idx;
        g_ow[i] = (idx < 7 && j < 27) ? ow[((j*Cc + c)*3 + ky)*3 + kx] : 0.f;
    }
}

// ---------------- K1: offset conv — 4 px x 7 j per thread ----------------
// block = (b,h) row: 128 threads = 4 j-quarter warps x 32 px lanes;
// lane handles px lane+32k, k=0..3.
__global__ void __launch_bounds__(128) k_offset(const float* __restrict__ ob) {
    __shared__ float wsm[64*32];     // [c][jq][8]  8 KB
    int t = threadIdx.x;
    int b = blockIdx.y, h = blockIdx.x;
    int lane = t & 31, jq = t >> 5;
    int j0 = jq * 7;

    // acc[k*4+p]: pixel k, j-pair p = (j0+2p, j0+2p+1); pair 3 hi is pad
    unsigned long long acc[16];
#pragma unroll
    for (int p = 0; p < 4; p++) {
        int j = j0 + 2*p;
        float lo = (j < 27)     ? __ldg(&ob[j])     : 0.f;
        float hi = (j + 1 < 27) ? __ldg(&ob[j + 1]) : 0.f;
        unsigned long long v = f2pack(lo, hi);
        acc[p] = v; acc[4+p] = v; acc[8+p] = v; acc[12+p] = v;
    }

    for (int tap = 0; tap < 9; tap++) {
        int ky = tap / 3, kx = tap % 3;
        __syncthreads();
        {   // stage this tap's packed weights (512 float4, 4 per thread)
            const float4* src = (const float4*)(g_ow + tap*64*32);
            float4* dst = (float4*)wsm;
            dst[t]       = src[t];
            dst[t + 128] = src[t + 128];
            dst[t + 256] = src[t + 256];
            dst[t + 384] = src[t + 384];
        }
        __syncthreads();
        int y = h + ky - 1;
        if ((unsigned)y < Hh) {
            const float* xrow = g_xt + (size_t)(b*Hh + y) * Ww * Cc;
            const float4* xp[4];
            bool val[4];
#pragma unroll
            for (int k = 0; k < 4; k++) {
                int xq = lane + 32*k + kx - 1;
                val[k] = ((unsigned)xq < Ww);
                int xc = min(max(xq, 0), Ww - 1);
                xp[k] = (const float4*)(xrow + (size_t)xc * Cc);
            }
            const float4 z4 = make_float4(0.f, 0.f, 0.f, 0.f);
#pragma unroll 4
            for (int c4 = 0; c4 < 16; c4++) {
                float4 xv0 = val[0] ? xp[0][c4] : z4;
                float4 xv1 = val[1] ? xp[1][c4] : z4;
                float4 xv2 = val[2] ? xp[2][c4] : z4;
                float4 xv3 = val[3] ? xp[3][c4] : z4;
                float xe0[4] = {xv0.x, xv0.y, xv0.z, xv0.w};
                float xe1[4] = {xv1.x, xv1.y, xv1.z, xv1.w};
                float xe2[4] = {xv2.x, xv2.y, xv2.z, xv2.w};
                float xe3[4] = {xv3.x, xv3.y, xv3.z, xv3.w};
#pragma unroll
                for (int e = 0; e < 4; e++) {
                    const ulonglong2* wr =
                        (const ulonglong2*)(wsm + (c4*4 + e)*32 + jq*8);
                    ulonglong2 wA = wr[0], wB = wr[1];   // pairs 0,1 / 2,3
                    unsigned long long s0 = f2pack(xe0[e], xe0[e]);
                    unsigned long long s1 = f2pack(xe1[e], xe1[e]);
                    unsigned long long s2 = f2pack(xe2[e], xe2[e]);
                    unsigned long long s3 = f2pack(xe3[e], xe3[e]);
                    ffma2(acc[0],  s0, wA.x); ffma2(acc[1],  s0, wA.y);
                    ffma2(acc[2],  s0, wB.x); ffma2(acc[3],  s0, wB.y);
                    ffma2(acc[4],  s1, wA.x); ffma2(acc[5],  s1, wA.y);
                    ffma2(acc[6],  s1, wB.x); ffma2(acc[7],  s1, wB.y);
                    ffma2(acc[8],  s2, wA.x); ffma2(acc[9],  s2, wA.y);
                    ffma2(acc[10], s2, wB.x); ffma2(acc[11], s2, wB.y);
                    ffma2(acc[12], s3, wA.x); ffma2(acc[13], s3, wA.y);
                    ffma2(acc[14], s3, wB.x); ffma2(acc[15], s3, wB.y);
                }
            }
        }
    }
    // write out: j = j0 + 0..6 for each of 4 pixels
#pragma unroll
    for (int k = 0; k < 4; k++) {
        int w = lane + 32*k;
        int base = (b*9)*HW + h*Ww + w;
        float a[8];
#pragma unroll
        for (int p = 0; p < 4; p++) f2unpack(acc[k*4 + p], a[2*p], a[2*p+1]);
#pragma unroll
        for (int u = 0; u < 7; u++) {
            int j = j0 + u;
            if (j < 9)        g_offx[base + j*HW]        = a[u];
            else if (j < 18)  g_offy[base + (j - 9)*HW]  = a[u];
            else if (j < 27)  g_mask[base + (j - 18)*HW] = 1.f / (1.f + expf(-a[u]));
        }
    }
}

// ---------------- K2: DCN sampling + GEMM (unchanged, best-known) ----------------
__global__ void __launch_bounds__(128, 8) k_dcn(const float* __restrict__ dcn_b,
                                                float* __restrict__ out) {
    __shared__ float ws[64*64];
    __shared__ float samp[64*33];

    int t    = threadIdx.x;
    int bb   = blockIdx.y, h = blockIdx.x, pq = blockIdx.z;
    int lane = t & 31,  wrp = t >> 5;
    int og   = t >> 4,  ps  = t & 15;

    unsigned long long acc[8];
#pragma unroll
    for (int i = 0; i < 8; i++) acc[i] = 0ULL;

    for (int tap = 0; tap < 9; tap++) {
        int ky = tap / 3, kx = tap % 3;
        __syncthreads();
        {
            const float4* src = (const float4*)(g_wt + tap*4096);
            float4* dst = (float4*)ws;
#pragma unroll
            for (int i = 0; i < 8; i++) dst[t + 128*i] = src[t + 128*i];
        }
#pragma unroll
        for (int i = 0; i < 8; i += 2) {
            int pp0 = wrp*8 + i, pp1 = pp0 + 1;
            int wq0 = pq*32 + pp0, wq1 = wq0 + 1;
            int ob0 = ((bb*9 + tap)*Hh + h)*Ww + wq0;
            int ob1 = ob0 + 1;
            float oy0 = __ldg(&g_offy[ob0]), ox0 = __ldg(&g_offx[ob0]), m0 = __ldg(&g_mask[ob0]);
            float oy1 = __ldg(&g_offy[ob1]), ox1 = __ldg(&g_offx[ob1]), m1 = __ldg(&g_mask[ob1]);

            float py0 = (float)(h - 1 + ky) + oy0, px0 = (float)(wq0 - 1 + kx) + ox0;
            float py1 = (float)(h - 1 + ky) + oy1, px1 = (float)(wq1 - 1 + kx) + ox1;
            float y0f0 = floorf(py0), x0f0 = floorf(px0);
            float y0f1 = floorf(py1), x0f1 = floorf(px1);
            float wy0 = py0 - y0f0, wx0 = px0 - x0f0;
            float wy1 = py1 - y0f1, wx1 = px1 - x0f1;
            float hy00 = (y0f0 >=  0.f && y0f0 <= 127.f) ? (1.f - wy0)*m0 : 0.f;
            float hy10 = (y0f0 >= -1.f && y0f0 <= 126.f) ? wy0*m0        : 0.f;
            float gx00 = (x0f0 >=  0.f && x0f0 <= 127.f) ? (1.f - wx0)   : 0.f;
            float gx10 = (x0f0 >= -1.f && x0f0 <= 126.f) ? wx0           : 0.f;
            float hy01 = (y0f1 >=  0.f && y0f1 <= 127.f) ? (1.f - wy1)*m1 : 0.f;
            float hy11 = (y0f1 >= -1.f && y0f1 <= 126.f) ? wy1*m1        : 0.f;
            float gx01 = (x0f1 >=  0.f && x0f1 <= 127.f) ? (1.f - wx1)   : 0.f;
            float gx11 = (x0f1 >= -1.f && x0f1 <= 126.f) ? wx1           : 0.f;
            int iy00 = (int)fminf(fmaxf(y0f0,      0.f), 127.f);
            int iy10 = (int)fminf(fmaxf(y0f0 + 1.f,0.f), 127.f);
            int ix00 = (int)fminf(fmaxf(x0f0,      0.f), 127.f);
            int ix10 = (int)fminf(fmaxf(x0f0 + 1.f,0.f), 127.f);
            int iy01 = (int)fminf(fmaxf(y0f1,      0.f), 127.f);
            int iy11 = (int)fminf(fmaxf(y0f1 + 1.f,0.f), 127.f);
            int ix01 = (int)fminf(fmaxf(x0f1,      0.f), 127.f);
            int ix11 = (int)fminf(fmaxf(x0f1 + 1.f,0.f), 127.f);
            float wA0 = hy00*gx00, wB0 = hy00*gx10, wC0 = hy10*gx00, wD0 = hy10*gx10;
            float wA1 = hy01*gx01, wB1 = hy01*gx11, wC1 = hy11*gx01, wD1 = hy11*gx11;
            const float* A0 = g_xt + (size_t)((bb*Hh + iy00)*Ww + ix00) * Cc;
            const float* B0 = g_xt + (size_t)((bb*Hh + iy00)*Ww + ix10) * Cc;
            const float* C0 = g_xt + (size_t)((bb*Hh + iy10)*Ww + ix00) * Cc;
            const float* D0 = g_xt + (size_t)((bb*Hh + iy10)*Ww + ix10) * Cc;
            const float* A1 = g_xt + (size_t)((bb*Hh + iy01)*Ww + ix01) * Cc;
            const float* B1 = g_xt + (size_t)((bb*Hh + iy01)*Ww + ix11) * Cc;
            const float* C1 = g_xt + (size_t)((bb*Hh + iy11)*Ww + ix01) * Cc;
            const float* D1 = g_xt + (size_t)((bb*Hh + iy11)*Ww + ix11) * Cc;
            float a0 = A0[lane],    b0 = B0[lane],    c0 = C0[lane],    d0 = D0[lane];
            float e0 = A0[lane+32], f0 = B0[lane+32], g0 = C0[lane+32], q0 = D0[lane+32];
            float a1 = A1[lane],    b1 = B1[lane],    c1 = C1[lane],    d1 = D1[lane];
            float e1 = A1[lane+32], f1 = B1[lane+32], g1 = C1[lane+32], q1 = D1[lane+32];
            samp[lane*33 + pp0]      = wA0*a0 + wB0*b0 + wC0*c0 + wD0*d0;
            samp[(lane+32)*33 + pp0] = wA0*e0 + wB0*f0 + wC0*g0 + wD0*q0;
            samp[lane*33 + pp1]      = wA1*a1 + wB1*b1 + wC1*c1 + wD1*d1;
            samp[(lane+32)*33 + pp1] = wA1*e1 + wB1*f1 + wC1*g1 + wD1*q1;
        }
        __syncthreads();
#pragma unroll 4
        for (int c = 0; c < 64; c++) {
            const float* srow = samp + c*33;
            float s0 = srow[ps], s1 = srow[ps + 16];
            unsigned long long p0 = f2pack(s0, s0), p1 = f2pack(s1, s1);
            const ulonglong2* wr = (const ulonglong2*)(ws + c*64 + og*8);
            ulonglong2 wa = wr[0], wb = wr[1];
            ffma2(acc[0], p0, wa.x); ffma2(acc[1], p0, wa.y);
            ffma2(acc[2], p0, wb.x); ffma2(acc[3], p0, wb.y);
            ffma2(acc[4], p1, wa.x); ffma2(acc[5], p1, wa.y);
            ffma2(acc[6], p1, wb.x); ffma2(acc[7], p1, wb.y);
        }
    }
#pragma unroll
    for (int k = 0; k < 2; k++) {
        int p = pq*32 + ps + 16*k;
#pragma unroll
        for (int j = 0; j < 4; j++) {
            float lo, hi; f2unpack(acc[k*4 + j], lo, hi);
            int o = og*8 + 2*j;
            out[(size_t)(bb*Oo + o    )*HW + h*Ww + p] = lo + __ldg(&dcn_b[o]);
            out[(size_t)(bb*Oo + o + 1)*HW + h*Ww + p] = hi + __ldg(&dcn_b[o+1]);
        }
    }
}

// ---------------- K3: per-channel stats ----------------
__global__ void k_stats(const float* __restrict__ out) {
    __shared__ float ssum[512], ssq[512];
    int o = blockIdx.x, t = threadIdx.x;
    float s = 0.f, q = 0.f;
    for (int i = t; i < Bn*HW; i += 512) {
        int b = i >> 14, j = i & (HW - 1);
        float v = out[(size_t)(b*Oo + o)*HW + j];
        s += v; q += v*v;
    }
    ssum[t] = s; ssq[t] = q;
    __syncthreads();
    for (int st = 256; st > 0; st >>= 1) {
        if (t < st) { ssum[t] += ssum[t+st]; ssq[t] += ssq[t+st]; }
        __syncthreads();
    }
    if (t == 0) { g_stats[o] = ssum[0]; g_stats[64 + o] = ssq[0]; }
}

// ---------------- K4: BN + ReLU ----------------
__global__ void k_norm(float* __restrict__ out,
                       const float* __restrict__ gamma,
                       const float* __restrict__ beta) {
    int i4 = blockIdx.x * 256 + threadIdx.x;
    int idx = i4 * 4;
    int o = (idx >> 14) & 63;
    const float invN = 1.f / (float)(Bn*HW);
    float s = g_stats[o], q = g_stats[64 + o];
    float mu  = s * invN;
    float var = fmaf(q, invN, -mu*mu);
    float rstd = rsqrtf(var + 1e-5f) * __ldg(&gamma[o]);
    float bt = __ldg(&beta[o]);
    float4 v = *(float4*)(out + idx);
    v.x = fmaxf((v.x - mu)*rstd + bt, 0.f);
    v.y = fmaxf((v.y - mu)*rstd + bt, 0.f);
    v.z = fmaxf((v.z - mu)*rstd + bt, 0.f);
    v.w = fmaxf((v.w - mu)*rstd + bt, 0.f);
    *(float4*)(out + idx) = v;
}

// ---------------- launcher ----------------
extern "C" void kernel_launch(void* const* d_in, const int* in_sizes, int n_in,
                              void* d_out, int out_size) {
    const float* x        = (const float*)d_in[0];
    const float* offset_w = (const float*)d_in[1];
    const float* offset_b = (const float*)d_in[2];
    const float* dcn_w    = (const float*)d_in[3];
    const float* dcn_b    = (const float*)d_in[4];
    const float* gamma    = (const float*)d_in[5];
    const float* beta     = (const float*)d_in[6];
    float* out = (float*)d_out;

    k_transpose<<<dim3(512, Bn), dim3(32, 8)>>>(x);
    k_wt<<<144, 256>>>(dcn_w);
    k_owt<<<72, 256>>>(offset_w);
    k_offset<<<dim3(Hh, Bn), 128>>>(offset_b);
    k_dcn<<<dim3(Hh, Bn, 4), 128>>>(dcn_b, out);
    k_stats<<<Oo, 512>>>(out);
    k_norm<<<(Bn*Oo*HW)/1024, 256>>>(out, gamma, beta);
}

// round 6
// speedup vs baseline: 1.3637x; 1.3637x over previous
#include <cuda_runtime.h>
#include <math.h>

#define Bn 4
#define Cc 64
#define Oo 64
#define Hh 128
#define Ww 128
#define HW (Hh*Ww)

// ---------------- device scratch ----------------
__device__ float g_xt[Bn*HW*Cc];      // x as [b][h][w][c]
__device__ float g_wt[9*Cc*Oo];       // dcn_w as [tap][c][o]
__device__ float g_ow[9*Cc*32];       // offset_w as [tap][c][jq][8], j = jq*7+idx (idx<7, j<27)
__device__ float g_offx[Bn*9*HW];
__device__ float g_offy[Bn*9*HW];
__device__ float g_mask[Bn*9*HW];
__device__ float g_stats[2*Oo];

// ---------------- f32x2 helpers ----------------
__device__ __forceinline__ unsigned long long f2pack(float lo, float hi) {
    unsigned long long r;
    asm("mov.b64 %0, {%1, %2};" : "=l"(r)
        : "r"(__float_as_uint(lo)), "r"(__float_as_uint(hi)));
    return r;
}
__device__ __forceinline__ void f2unpack(unsigned long long v, float &lo, float &hi) {
    unsigned int a, b;
    asm("mov.b64 {%0, %1}, %2;" : "=r"(a), "=r"(b) : "l"(v));
    lo = __uint_as_float(a); hi = __uint_as_float(b);
}
__device__ __forceinline__ void ffma2(unsigned long long &d,
                                      unsigned long long a, unsigned long long b) {
    asm("fma.rn.f32x2 %0, %1, %2, %0;" : "+l"(d) : "l"(a), "l"(b));
}

// ---------------- K0: NCHW -> NHWC ----------------
__global__ void k_transpose(const float* __restrict__ x) {
    __shared__ float tile[32][65];
    int b = blockIdx.y, hw0 = blockIdx.x * 32;
    int tx = threadIdx.x, ty = threadIdx.y;
#pragma unroll
    for (int cc = 0; cc < 8; cc++) {
        int c = cc * 8 + ty;
        tile[tx][c] = x[(b*Cc + c)*HW + hw0 + tx];
    }
    __syncthreads();
#pragma unroll
    for (int rr = 0; rr < 4; rr++) {
        int hw = rr * 8 + ty;
        float* dst = g_xt + (size_t)(b*HW + hw0 + hw) * Cc;
        dst[tx]      = tile[hw][tx];
        dst[tx + 32] = tile[hw][tx + 32];
    }
}

// ---------------- K0b: weight re-layouts ----------------
__global__ void k_wt(const float* __restrict__ dcn_w) {
    int i = blockIdx.x * 256 + threadIdx.x;
    if (i < 9*Cc*Oo) {
        int o = i & 63, c = (i >> 6) & 63, k = i >> 12;
        g_wt[i] = dcn_w[(o*Cc + c)*9 + k];
    }
}
// offset_w -> [tap][c][jq][8]: slot idx of quarter jq maps to j = jq*7+idx (idx<7, j<27)
__global__ void k_owt(const float* __restrict__ ow) {
    int i = blockIdx.x * 256 + threadIdx.x;
    if (i < 9*Cc*32) {
        int slot = i & 31, c = (i >> 5) & 63, tap = i >> 11;
        int ky = tap / 3, kx = tap % 3;
        int jq = slot >> 3, idx = slot & 7;
        int j = jq*7 + idx;
        g_ow[i] = (idx < 7 && j < 27) ? ow[((j*Cc + c)*3 + ky)*3 + kx] : 0.f;
    }
}

// ---------------- K1: offset conv — smem-staged, k_dcn-style ----------------
// block = (b, h, px-half): 64 px; 128 threads.
// Per tap: coalesced gather (lane=channel) into xs[c][px], then GEMM from smem.
// Thread GEMM tile: j-quarter (7 j) x 2 px (ps, ps+32).
__global__ void __launch_bounds__(128) k_offset(const float* __restrict__ ob) {
    __shared__ float wsm[64*32];     // [c][jq][8]   8 KB
    __shared__ float xs[64*65];      // [c][px] stride 65  16.6 KB
    int t = threadIdx.x;
    int b = blockIdx.y, h = blockIdx.x, ph = blockIdx.z;
    int w0 = ph * 64;
    int lane = t & 31, wrp = t >> 5;
    int jq = wrp, ps = lane;
    int j0 = jq * 7;

    unsigned long long acc[8];       // [px 2][j-pair 4]
#pragma unroll
    for (int p = 0; p < 4; p++) {
        int j = j0 + 2*p;
        float lo = (j < 27)     ? __ldg(&ob[j])     : 0.f;
        float hi = (j + 1 < 27) ? __ldg(&ob[j + 1]) : 0.f;
        unsigned long long v = f2pack(lo, hi);
        acc[p] = v; acc[4 + p] = v;
    }

    for (int tap = 0; tap < 9; tap++) {
        int ky = tap / 3, kx = tap % 3;
        __syncthreads();
        {   // stage this tap's packed weights (512 float4, 4 per thread)
            const float4* src = (const float4*)(g_ow + tap*64*32);
            float4* dst = (float4*)wsm;
            dst[t]       = src[t];
            dst[t + 128] = src[t + 128];
            dst[t + 256] = src[t + 256];
            dst[t + 384] = src[t + 384];
        }
        // stage shifted x row: warp per pixel, lane = channel (coalesced 128B)
        int y = h + ky - 1;
        if ((unsigned)y < Hh) {
            const float* xrow = g_xt + (size_t)(b*Hh + y) * Ww * Cc;
#pragma unroll
            for (int pp = wrp; pp < 64; pp += 4) {
                int xq = w0 + pp + kx - 1;
                bool v = ((unsigned)xq < Ww);
                const float* src = xrow + (size_t)(v ? xq : 0) * Cc;
                float v0 = v ? src[lane]      : 0.f;
                float v1 = v ? src[lane + 32] : 0.f;
                xs[lane*65 + pp]        = v0;
                xs[(lane + 32)*65 + pp] = v1;
            }
        } else {
#pragma unroll
            for (int pp = wrp; pp < 64; pp += 4) {
                xs[lane*65 + pp]        = 0.f;
                xs[(lane + 32)*65 + pp] = 0.f;
            }
        }
        __syncthreads();
        // GEMM: per c: 2 scalar LDS + 2 broadcast LDS.128 + 8 FFMA2
#pragma unroll 4
        for (int c = 0; c < 64; c++) {
            const float* srow = xs + c*65;
            float s0 = srow[ps], s1 = srow[ps + 32];
            unsigned long long p0 = f2pack(s0, s0), p1 = f2pack(s1, s1);
            const ulonglong2* wr = (const ulonglong2*)(wsm + c*32 + jq*8);
            ulonglong2 wA = wr[0], wB = wr[1];
            ffma2(acc[0], p0, wA.x); ffma2(acc[1], p0, wA.y);
            ffma2(acc[2], p0, wB.x); ffma2(acc[3], p0, wB.y);
            ffma2(acc[4], p1, wA.x); ffma2(acc[5], p1, wA.y);
            ffma2(acc[6], p1, wB.x); ffma2(acc[7], p1, wB.y);
        }
    }
    // write out: 2 px x 7 j (predicated scatter into offx/offy/mask planes)
#pragma unroll
    for (int k = 0; k < 2; k++) {
        int w = w0 + ps + 32*k;
        int base = (b*9)*HW + h*Ww + w;
        float a[8];
#pragma unroll
        for (int p = 0; p < 4; p++) f2unpack(acc[k*4 + p], a[2*p], a[2*p+1]);
#pragma unroll
        for (int u = 0; u < 7; u++) {
            int j = j0 + u;
            if (j < 9)        g_offx[base + j*HW]        = a[u];
            else if (j < 18)  g_offy[base + (j - 9)*HW]  = a[u];
            else if (j < 27)  g_mask[base + (j - 18)*HW] = 1.f / (1.f + expf(-a[u]));
        }
    }
}

// ---------------- K2: DCN sampling + GEMM (unchanged, best-known) ----------------
__global__ void __launch_bounds__(128, 8) k_dcn(const float* __restrict__ dcn_b,
                                                float* __restrict__ out) {
    __shared__ float ws[64*64];
    __shared__ float samp[64*33];

    int t    = threadIdx.x;
    int bb   = blockIdx.y, h = blockIdx.x, pq = blockIdx.z;
    int lane = t & 31,  wrp = t >> 5;
    int og   = t >> 4,  ps  = t & 15;

    unsigned long long acc[8];
#pragma unroll
    for (int i = 0; i < 8; i++) acc[i] = 0ULL;

    for (int tap = 0; tap < 9; tap++) {
        int ky = tap / 3, kx = tap % 3;
        __syncthreads();
        {
            const float4* src = (const float4*)(g_wt + tap*4096);
            float4* dst = (float4*)ws;
#pragma unroll
            for (int i = 0; i < 8; i++) dst[t + 128*i] = src[t + 128*i];
        }
#pragma unroll
        for (int i = 0; i < 8; i += 2) {
            int pp0 = wrp*8 + i, pp1 = pp0 + 1;
            int wq0 = pq*32 + pp0, wq1 = wq0 + 1;
            int ob0 = ((bb*9 + tap)*Hh + h)*Ww + wq0;
            int ob1 = ob0 + 1;
            float oy0 = __ldg(&g_offy[ob0]), ox0 = __ldg(&g_offx[ob0]), m0 = __ldg(&g_mask[ob0]);
            float oy1 = __ldg(&g_offy[ob1]), ox1 = __ldg(&g_offx[ob1]), m1 = __ldg(&g_mask[ob1]);

            float py0 = (float)(h - 1 + ky) + oy0, px0 = (float)(wq0 - 1 + kx) + ox0;
            float py1 = (float)(h - 1 + ky) + oy1, px1 = (float)(wq1 - 1 + kx) + ox1;
            float y0f0 = floorf(py0), x0f0 = floorf(px0);
            float y0f1 = floorf(py1), x0f1 = floorf(px1);
            float wy0 = py0 - y0f0, wx0 = px0 - x0f0;
            float wy1 = py1 - y0f1, wx1 = px1 - x0f1;
            float hy00 = (y0f0 >=  0.f && y0f0 <= 127.f) ? (1.f - wy0)*m0 : 0.f;
            float hy10 = (y0f0 >= -1.f && y0f0 <= 126.f) ? wy0*m0        : 0.f;
            float gx00 = (x0f0 >=  0.f && x0f0 <= 127.f) ? (1.f - wx0)   : 0.f;
            float gx10 = (x0f0 >= -1.f && x0f0 <= 126.f) ? wx0           : 0.f;
            float hy01 = (y0f1 >=  0.f && y0f1 <= 127.f) ? (1.f - wy1)*m1 : 0.f;
            float hy11 = (y0f1 >= -1.f && y0f1 <= 126.f) ? wy1*m1        : 0.f;
            float gx01 = (x0f1 >=  0.f && x0f1 <= 127.f) ? (1.f - wx1)   : 0.f;
            float gx11 = (x0f1 >= -1.f && x0f1 <= 126.f) ? wx1           : 0.f;
            int iy00 = (int)fminf(fmaxf(y0f0,      0.f), 127.f);
            int iy10 = (int)fminf(fmaxf(y0f0 + 1.f,0.f), 127.f);
            int ix00 = (int)fminf(fmaxf(x0f0,      0.f), 127.f);
            int ix10 = (int)fminf(fmaxf(x0f0 + 1.f,0.f), 127.f);
            int iy01 = (int)fminf(fmaxf(y0f1,      0.f), 127.f);
            int iy11 = (int)fminf(fmaxf(y0f1 + 1.f,0.f), 127.f);
            int ix01 = (int)fminf(fmaxf(x0f1,      0.f), 127.f);
            int ix11 = (int)fminf(fmaxf(x0f1 + 1.f,0.f), 127.f);
            float wA0 = hy00*gx00, wB0 = hy00*gx10, wC0 = hy10*gx00, wD0 = hy10*gx10;
            float wA1 = hy01*gx01, wB1 = hy01*gx11, wC1 = hy11*gx01, wD1 = hy11*gx11;
            const float* A0 = g_xt + (size_t)((bb*Hh + iy00)*Ww + ix00) * Cc;
            const float* B0 = g_xt + (size_t)((bb*Hh + iy00)*Ww + ix10) * Cc;
            const float* C0 = g_xt + (size_t)((bb*Hh + iy10)*Ww + ix00) * Cc;
            const float* D0 = g_xt + (size_t)((bb*Hh + iy10)*Ww + ix10) * Cc;
            const float* A1 = g_xt + (size_t)((bb*Hh + iy01)*Ww + ix01) * Cc;
            const float* B1 = g_xt + (size_t)((bb*Hh + iy01)*Ww + ix11) * Cc;
            const float* C1 = g_xt + (size_t)((bb*Hh + iy11)*Ww + ix01) * Cc;
            const float* D1 = g_xt + (size_t)((bb*Hh + iy11)*Ww + ix11) * Cc;
            float a0 = A0[lane],    b0 = B0[lane],    c0 = C0[lane],    d0 = D0[lane];
            float e0 = A0[lane+32], f0 = B0[lane+32], g0 = C0[lane+32], q0 = D0[lane+32];
            float a1 = A1[lane],    b1 = B1[lane],    c1 = C1[lane],    d1 = D1[lane];
            float e1 = A1[lane+32], f1 = B1[lane+32], g1 = C1[lane+32], q1 = D1[lane+32];
            samp[lane*33 + pp0]      = wA0*a0 + wB0*b0 + wC0*c0 + wD0*d0;
            samp[(lane+32)*33 + pp0] = wA0*e0 + wB0*f0 + wC0*g0 + wD0*q0;
            samp[lane*33 + pp1]      = wA1*a1 + wB1*b1 + wC1*c1 + wD1*d1;
            samp[(lane+32)*33 + pp1] = wA1*e1 + wB1*f1 + wC1*g1 + wD1*q1;
        }
        __syncthreads();
#pragma unroll 4
        for (int c = 0; c < 64; c++) {
            const float* srow = samp + c*33;
            float s0 = srow[ps], s1 = srow[ps + 16];
            unsigned long long p0 = f2pack(s0, s0), p1 = f2pack(s1, s1);
            const ulonglong2* wr = (const ulonglong2*)(ws + c*64 + og*8);
            ulonglong2 wa = wr[0], wb = wr[1];
            ffma2(acc[0], p0, wa.x); ffma2(acc[1], p0, wa.y);
            ffma2(acc[2], p0, wb.x); ffma2(acc[3], p0, wb.y);
            ffma2(acc[4], p1, wa.x); ffma2(acc[5], p1, wa.y);
            ffma2(acc[6], p1, wb.x); ffma2(acc[7], p1, wb.y);
        }
    }
#pragma unroll
    for (int k = 0; k < 2; k++) {
        int p = pq*32 + ps + 16*k;
#pragma unroll
        for (int j = 0; j < 4; j++) {
            float lo, hi; f2unpack(acc[k*4 + j], lo, hi);
            int o = og*8 + 2*j;
            out[(size_t)(bb*Oo + o    )*HW + h*Ww + p] = lo + __ldg(&dcn_b[o]);
            out[(size_t)(bb*Oo + o + 1)*HW + h*Ww + p] = hi + __ldg(&dcn_b[o+1]);
        }
    }
}

// ---------------- K3: per-channel stats ----------------
__global__ void k_stats(const float* __restrict__ out) {
    __shared__ float ssum[512], ssq[512];
    int o = blockIdx.x, t = threadIdx.x;
    float s = 0.f, q = 0.f;
    for (int i = t; i < Bn*HW; i += 512) {
        int b = i >> 14, j = i & (HW - 1);
        float v = out[(size_t)(b*Oo + o)*HW + j];
        s += v; q += v*v;
    }
    ssum[t] = s; ssq[t] = q;
    __syncthreads();
    for (int st = 256; st > 0; st >>= 1) {
        if (t < st) { ssum[t] += ssum[t+st]; ssq[t] += ssq[t+st]; }
        __syncthreads();
    }
    if (t == 0) { g_stats[o] = ssum[0]; g_stats[64 + o] = ssq[0]; }
}

// ---------------- K4: BN + ReLU ----------------
__global__ void k_norm(float* __restrict__ out,
                       const float* __restrict__ gamma,
                       const float* __restrict__ beta) {
    int i4 = blockIdx.x * 256 + threadIdx.x;
    int idx = i4 * 4;
    int o = (idx >> 14) & 63;
    const float invN = 1.f / (float)(Bn*HW);
    float s = g_stats[o], q = g_stats[64 + o];
    float mu  = s * invN;
    float var = fmaf(q, invN, -mu*mu);
    float rstd = rsqrtf(var + 1e-5f) * __ldg(&gamma[o]);
    float bt = __ldg(&beta[o]);
    float4 v = *(float4*)(out + idx);
    v.x = fmaxf((v.x - mu)*rstd + bt, 0.f);
    v.y = fmaxf((v.y - mu)*rstd + bt, 0.f);
    v.z = fmaxf((v.z - mu)*rstd + bt, 0.f);
    v.w = fmaxf((v.w - mu)*rstd + bt, 0.f);
    *(float4*)(out + idx) = v;
}

// ---------------- launcher ----------------
extern "C" void kernel_launch(void* const* d_in, const int* in_sizes, int n_in,
                              void* d_out, int out_size) {
    const float* x        = (const float*)d_in[0];
    const float* offset_w = (const float*)d_in[1];
    const float* offset_b = (const float*)d_in[2];
    const float* dcn_w    = (const float*)d_in[3];
    const float* dcn_b    = (const float*)d_in[4];
    const float* gamma    = (const float*)d_in[5];
    const float* beta     = (const float*)d_in[6];
    float* out = (float*)d_out;

    k_transpose<<<dim3(512, Bn), dim3(32, 8)>>>(x);
    k_wt<<<144, 256>>>(dcn_w);
    k_owt<<<72, 256>>>(offset_w);
    k_offset<<<dim3(Hh, Bn, 2), 128>>>(offset_b);
    k_dcn<<<dim3(Hh, Bn, 4), 128>>>(dcn_b, out);
    k_stats<<<Oo, 512>>>(out);
    k_norm<<<(Bn*Oo*HW)/1024, 256>>>(out, gamma, beta);
}